// round 11
// baseline (speedup 1.0000x reference)
#include <cuda_runtime.h>

// Problem constants
#define I_ 3
#define H_ 2048
#define O_ 2
#define R_ 2
#define S_ 4
#define G_ 7
#define B_ 32
#define T_ 512
#define ALPHA_ 0.2f
#define DECAY_ 0.8f
#define NSTD_ 0.05f

#define NTHREADS 512
#define NWARPS (NTHREADS / 32)   // 16
#define EPT 4                    // per batch; 512*4 = 2048 = H
#define NPAIR (EPT / 2)          // 2
#define NBATCH 2                 // batches per CTA
#define NPART (NWARPS * 8)       // 128 partials per buffer (8 ch)

typedef unsigned long long u64;

// ---- f32x2 packed helpers ----
__device__ __forceinline__ u64 pack2(float lo, float hi) {
    u64 r; asm("mov.b64 %0, {%1,%2};" : "=l"(r) : "f"(lo), "f"(hi)); return r;
}
__device__ __forceinline__ void unpack2(u64 v, float& lo, float& hi) {
    asm("mov.b64 {%0,%1}, %2;" : "=f"(lo), "=f"(hi) : "l"(v));
}
__device__ __forceinline__ u64 fma2(u64 a, u64 b, u64 c) {
    u64 d; asm("fma.rn.f32x2 %0, %1, %2, %3;" : "=l"(d) : "l"(a), "l"(b), "l"(c)); return d;
}
__device__ __forceinline__ u64 mul2(u64 a, u64 b) {
    u64 d; asm("mul.rn.f32x2 %0, %1, %2;" : "=l"(d) : "l"(a), "l"(b)); return d;
}
__device__ __forceinline__ u64 add2(u64 a, u64 b) {
    u64 d; asm("add.rn.f32x2 %0, %1, %2;" : "=l"(d) : "l"(a), "l"(b)); return d;
}
__device__ __forceinline__ float ex2f(float x) {
    float y; asm("ex2.approx.f32 %0, %1;" : "=f"(y) : "f"(x)); return y;
}
__device__ __forceinline__ float rcpf(float x) {
    float y; asm("rcp.approx.f32 %0, %1;" : "=f"(y) : "f"(x)); return y;
}
// packed tanh: 1 - 2/(1+exp(2x)) — same precision class as R4-R10 (rel_err 6e-6)
__device__ __forceinline__ u64 tanh2(u64 hp, u64 c_2log2e, u64 c_one, u64 c_neg2) {
    u64 y = mul2(hp, c_2log2e);
    float y0, y1; unpack2(y, y0, y1);
    float e0 = ex2f(y0), e1 = ex2f(y1);
    u64 dp = add2(pack2(e0, e1), c_one);
    float d0, d1; unpack2(dp, d0, d1);
    float r0 = rcpf(d0), r1 = rcpf(d1);
    return fma2(pack2(r0, r1), c_neg2, c_one);
}

__global__ __launch_bounds__(NTHREADS, 1)
void lowrank_rnn_kernel(const float* __restrict__ input,   // (B,T,I)
                        const float* __restrict__ noise,   // (B,T,H)
                        const float* __restrict__ wi,      // (I,S,G)
                        const float* __restrict__ unitwi,  // (I,S,1)
                        const float* __restrict__ m,       // (R,S,G)
                        const float* __restrict__ n,       // (R,S,G)
                        const float* __restrict__ unitm,   // (R,S,1)
                        const float* __restrict__ unitn,   // (R,S,1)
                        const float* __restrict__ wo,      // (O,S,G)
                        const float* __restrict__ h0,      // (S,G)
                        const float* __restrict__ unith0,  // (S,1)
                        const float* __restrict__ bias,    // (S,1)
                        const float* __restrict__ gb,      // (G,H)
                        const float* __restrict__ uv,      // (1,H)
                        const float* __restrict__ sup,     // (S,H)
                        float* __restrict__ out)           // out(B,T,O) ++ traj(B,T,H)
{
    const int b0   = blockIdx.x * NBATCH;        // batches b0, b0+1
    const int tid  = threadIdx.x;
    const int lane = tid & 31;
    const int warp = tid >> 5;
    const unsigned FULL = 0xffffffffu;

    // double-buffered warp partials: [warp][8 slots]
    // slot = (batch<<2) | chperm, chperm: 0=n0, 1=wo0, 2=n1, 3=wo1
    __shared__ float s_red[2][NPART];

    // ------------------------------------------------------------------
    // Phase 1: per-element effective weights (SHARED across batches).
    // ------------------------------------------------------------------
    float f_h[EPT];
    float f_m0[EPT], f_m1[EPT], f_n0[EPT], f_n1[EPT];
    float f_wo0[EPT], f_wo1[EPT], f_bias[EPT];
    float f_wi0[EPT], f_wi1[EPT], f_wi2[EPT];

#pragma unroll
    for (int e = 0; e < EPT; e++) {
        const int hidx = tid * EPT + e;
        float gvec[G_];
#pragma unroll
        for (int g = 0; g < G_; g++) gvec[g] = gb[g * H_ + hidx];
        const float uvh = uv[hidx];

        float awi0 = 0.f, awi1 = 0.f, awi2 = 0.f;
        float am0 = 0.f, am1 = 0.f, an0 = 0.f, an1 = 0.f;
        float awo0 = 0.f, awo1 = 0.f, ah0 = 0.f, ab = 0.f;

#pragma unroll
        for (int s = 0; s < S_; s++) {
            const float su = sup[s * H_ + hidx];

            float d0 = 0.f, d1 = 0.f, d2 = 0.f;
#pragma unroll
            for (int g = 0; g < G_; g++) {
                d0 += wi[(0 * S_ + s) * G_ + g] * gvec[g];
                d1 += wi[(1 * S_ + s) * G_ + g] * gvec[g];
                d2 += wi[(2 * S_ + s) * G_ + g] * gvec[g];
            }
            awi0 += (d0 + unitwi[0 * S_ + s] * uvh) * su;
            awi1 += (d1 + unitwi[1 * S_ + s] * uvh) * su;
            awi2 += (d2 + unitwi[2 * S_ + s] * uvh) * su;

            float dm0 = 0.f, dm1 = 0.f, dn0 = 0.f, dn1 = 0.f;
#pragma unroll
            for (int g = 0; g < G_; g++) {
                dm0 += m[(0 * S_ + s) * G_ + g] * gvec[g];
                dm1 += m[(1 * S_ + s) * G_ + g] * gvec[g];
                dn0 += n[(0 * S_ + s) * G_ + g] * gvec[g];
                dn1 += n[(1 * S_ + s) * G_ + g] * gvec[g];
            }
            am0 += (dm0 + unitm[0 * S_ + s] * uvh) * su;
            am1 += (dm1 + unitm[1 * S_ + s] * uvh) * su;
            an0 += (dn0 + unitn[0 * S_ + s] * uvh) * su;
            an1 += (dn1 + unitn[1 * S_ + s] * uvh) * su;

            float do0 = 0.f, do1 = 0.f, dh = 0.f;
#pragma unroll
            for (int g = 0; g < G_; g++) {
                do0 += wo[(0 * S_ + s) * G_ + g] * gvec[g];
                do1 += wo[(1 * S_ + s) * G_ + g] * gvec[g];
                dh  += h0[s * G_ + g] * gvec[g];
            }
            awo0 += do0 * su;
            awo1 += do1 * su;
            ah0  += dh * su + unith0[s] * uvh * su;
            ab   += bias[s] * uvh * su;
        }
        f_h[e]   = ah0;
        f_m0[e]  = ALPHA_ * am0;  f_m1[e]  = ALPHA_ * am1;
        f_n0[e]  = an0;           f_n1[e]  = an1;
        f_wo0[e] = awo0;          f_wo1[e] = awo1;
        f_bias[e] = ab;
        f_wi0[e] = ALPHA_ * awi0; f_wi1[e] = ALPHA_ * awi1;
        f_wi2[e] = ALPHA_ * awi2;
    }

    // Packed constants (shared) + per-batch state
    u64 p_m0[NPAIR], p_m1[NPAIR];
    u64 p_wi0[NPAIR], p_wi1[NPAIR], p_wi2[NPAIR], p_bias[NPAIR];
    u64 p_n01[EPT], p_wo01[EPT];
#pragma unroll
    for (int p = 0; p < NPAIR; p++) {
        p_m0[p]   = pack2(f_m0[2 * p],  f_m0[2 * p + 1]);
        p_m1[p]   = pack2(f_m1[2 * p],  f_m1[2 * p + 1]);
        p_wi0[p]  = pack2(f_wi0[2 * p], f_wi0[2 * p + 1]);
        p_wi1[p]  = pack2(f_wi1[2 * p], f_wi1[2 * p + 1]);
        p_wi2[p]  = pack2(f_wi2[2 * p], f_wi2[2 * p + 1]);
        p_bias[p] = pack2(f_bias[2 * p], f_bias[2 * p + 1]);
    }
#pragma unroll
    for (int e = 0; e < EPT; e++) {
        p_n01[e]  = pack2(f_n0[e],  f_n1[e]);
        p_wo01[e] = pack2(f_wo0[e], f_wo1[e]);
    }
    const u64 C_DECAY2  = pack2(DECAY_, DECAY_);
    const u64 C_NSTD2   = pack2(NSTD_, NSTD_);
    const u64 C_2LOG2E2 = pack2(2.8853900817779268f, 2.8853900817779268f);
    const u64 C_ONE2    = pack2(1.0f, 1.0f);
    const u64 C_NEG22   = pack2(-2.0f, -2.0f);

    // Per-batch state: h, pr
    u64 hA[NPAIR], hB[NPAIR];
    hA[0] = hB[0] = pack2(f_h[0], f_h[1]);
    hA[1] = hB[1] = pack2(f_h[2], f_h[3]);

    u64 prA_A, prB_A, prA_B, prB_B;   // (n0,n1) and (wo0,wo1) per batch
    {
        u64 pa = pack2(0.f, 0.f), pb = pack2(0.f, 0.f);
#pragma unroll
        for (int p = 0; p < NPAIR; p++) {
            u64 th = tanh2(hA[p], C_2LOG2E2, C_ONE2, C_NEG22);
            float r0, r1; unpack2(th, r0, r1);
            pa = fma2(pack2(r0, r0), p_n01[2 * p],      pa);
            pb = fma2(pack2(r0, r0), p_wo01[2 * p],     pb);
            pa = fma2(pack2(r1, r1), p_n01[2 * p + 1],  pa);
            pb = fma2(pack2(r1, r1), p_wo01[2 * p + 1], pb);
        }
        prA_A = prA_B = pa;
        prB_A = prB_B = pb;
    }

    // Pointers
    const float* zbA = noise + (size_t)b0 * T_ * H_;
    const float* zbB = zbA + (size_t)T_ * H_;
    const float* xbA = input + (size_t)b0 * T_ * I_;
    const float* xbB = xbA + (size_t)T_ * I_;
    float* outpA  = out + (size_t)b0 * T_ * O_;
    float* outpB  = outpA + (size_t)T_ * O_;
    float* trajpA = out + (size_t)B_ * T_ * O_ + (size_t)b0 * T_ * H_;
    float* trajpB = trajpA + (size_t)T_ * H_;

    // Preload step-0 noise/input
    float4 zcA = *(const float4*)(zbA + tid * 4);
    float4 zcB = *(const float4*)(zbB + tid * 4);
    float xcA0 = xbA[0], xcA1 = xbA[1], xcA2 = xbA[2];
    float xcB0 = xbB[0], xcB1 = xbB[1], xcB2 = xbB[2];

    for (int t = 0; t < T_; t++) {
        const int buf = t & 1;

        // ---- stage A: 8-channel fold (batch level + R4 4-ch fold) ----
        float v;
        {
            // batch fold (xor 4): keep own-batch on bit2=0 lanes
            const bool kb = !(lane & 4);
            u64 sAx = kb ? prA_B : prA_A;
            u64 sBx = kb ? prB_B : prB_A;
            u64 rAx = __shfl_xor_sync(FULL, sAx, 4);
            u64 rBx = __shfl_xor_sync(FULL, sBx, 4);
            u64 qA = add2(kb ? prA_A : prA_B, rAx);   // (n0,n1) of my batch
            u64 qB = add2(kb ? prB_A : prB_B, rBx);   // (wo0,wo1)
            float px, py, pz, pw;
            unpack2(qA, px, py);
            unpack2(qB, pz, pw);
            const bool k1 = !(lane & 1);
            float sA = k1 ? pz : px;
            float rA = __shfl_xor_sync(FULL, sA, 1);
            float v0 = (k1 ? px : pz) + rA;
            float sB = k1 ? pw : py;
            float rB = __shfl_xor_sync(FULL, sB, 1);
            float v1 = (k1 ? py : pw) + rB;
            const bool k2 = !(lane & 2);
            float sC = k2 ? v1 : v0;
            float rC = __shfl_xor_sync(FULL, sC, 2);
            v = (k2 ? v0 : v1) + rC;
            v += __shfl_xor_sync(FULL, v, 8);
            v += __shfl_xor_sync(FULL, v, 16);
        }
        // lane 0-7: slot = (lane&4) | chperm(lane&3)
        if (lane < 8) s_red[buf][warp * 8 + lane] = v;

        // ---- shadow: traj stores, z/x prefetch (t+1), hb for both ----
        if (t > 0) {
            float a0, a1, a2, a3;
            unpack2(hA[0], a0, a1);
            unpack2(hA[1], a2, a3);
            *(float4*)(trajpA + (size_t)(t - 1) * H_ + tid * 4) =
                make_float4(a0, a1, a2, a3);
            unpack2(hB[0], a0, a1);
            unpack2(hB[1], a2, a3);
            *(float4*)(trajpB + (size_t)(t - 1) * H_ + tid * 4) =
                make_float4(a0, a1, a2, a3);
        }
        const int tp = (t + 1 < T_) ? (t + 1) : (T_ - 1);
        float4 znA = *(const float4*)(zbA + (size_t)tp * H_ + tid * 4);
        float4 znB = *(const float4*)(zbB + (size_t)tp * H_ + tid * 4);
        const float xnA0 = xbA[tp * I_ + 0];
        const float xnA1 = xbA[tp * I_ + 1];
        const float xnA2 = xbA[tp * I_ + 2];
        const float xnB0 = xbB[tp * I_ + 0];
        const float xnB1 = xbB[tp * I_ + 1];
        const float xnB2 = xbB[tp * I_ + 2];

        u64 hbA[NPAIR], hbB[NPAIR];
        {
            u64 x0 = pack2(xcA0, xcA0);
            u64 x1 = pack2(xcA1, xcA1);
            u64 x2 = pack2(xcA2, xcA2);
            u64 z0 = pack2(zcA.x, zcA.y);
            u64 z1 = pack2(zcA.z, zcA.w);
            hbA[0] = fma2(hA[0], C_DECAY2, p_bias[0]);
            hbA[0] = fma2(z0, C_NSTD2, hbA[0]);
            hbA[1] = fma2(hA[1], C_DECAY2, p_bias[1]);
            hbA[1] = fma2(z1, C_NSTD2, hbA[1]);
#pragma unroll
            for (int p = 0; p < NPAIR; p++) {
                hbA[p] = fma2(x0, p_wi0[p], hbA[p]);
                hbA[p] = fma2(x1, p_wi1[p], hbA[p]);
                hbA[p] = fma2(x2, p_wi2[p], hbA[p]);
            }
            x0 = pack2(xcB0, xcB0);
            x1 = pack2(xcB1, xcB1);
            x2 = pack2(xcB2, xcB2);
            z0 = pack2(zcB.x, zcB.y);
            z1 = pack2(zcB.z, zcB.w);
            hbB[0] = fma2(hB[0], C_DECAY2, p_bias[0]);
            hbB[0] = fma2(z0, C_NSTD2, hbB[0]);
            hbB[1] = fma2(hB[1], C_DECAY2, p_bias[1]);
            hbB[1] = fma2(z1, C_NSTD2, hbB[1]);
#pragma unroll
            for (int p = 0; p < NPAIR; p++) {
                hbB[p] = fma2(x0, p_wi0[p], hbB[p]);
                hbB[p] = fma2(x1, p_wi1[p], hbB[p]);
                hbB[p] = fma2(x2, p_wi2[p], hbB[p]);
            }
        }

        __syncthreads();   // partials visible

        // ---- stage C: 4 LDS + 3 ADD + xor8/16 butterfly + broadcasts ----
        float Sn0A, Sn1A, Sn0B, Sn1B;
        {
            float u = s_red[buf][lane] + s_red[buf][lane + 32]
                    + s_red[buf][lane + 64] + s_red[buf][lane + 96];
            u += __shfl_xor_sync(FULL, u, 8);
            u += __shfl_xor_sync(FULL, u, 16);
            // lane&7: 0=n0A,1=wo0A,2=n1A,3=wo1A,4=n0B,5=wo0B,6=n1B,7=wo1B
            Sn0A = __shfl_sync(FULL, u, 0);
            Sn1A = __shfl_sync(FULL, u, 2);
            Sn0B = __shfl_sync(FULL, u, 4);
            Sn1B = __shfl_sync(FULL, u, 6);
            if (warp == 0 && t > 0) {
                if (lane == 1) outpA[(t - 1) * O_ + 0] = u;
                if (lane == 3) outpA[(t - 1) * O_ + 1] = u;
                if (lane == 5) outpB[(t - 1) * O_ + 0] = u;
                if (lane == 7) outpB[(t - 1) * O_ + 1] = u;
            }
        }

        // ---- stage D: both batches ----
        {
            u64 S0 = pack2(Sn0A, Sn0A);
            u64 S1 = pack2(Sn1A, Sn1A);
            prA_A = pack2(0.f, 0.f);
            prB_A = pack2(0.f, 0.f);
#pragma unroll
            for (int p = 0; p < NPAIR; p++) {
                u64 h = fma2(S0, p_m0[p], hbA[p]);
                h = fma2(S1, p_m1[p], h);
                hA[p] = h;
                u64 th = tanh2(h, C_2LOG2E2, C_ONE2, C_NEG22);
                float r0, r1; unpack2(th, r0, r1);
                prA_A = fma2(pack2(r0, r0), p_n01[2 * p],      prA_A);
                prB_A = fma2(pack2(r0, r0), p_wo01[2 * p],     prB_A);
                prA_A = fma2(pack2(r1, r1), p_n01[2 * p + 1],  prA_A);
                prB_A = fma2(pack2(r1, r1), p_wo01[2 * p + 1], prB_A);
            }
            S0 = pack2(Sn0B, Sn0B);
            S1 = pack2(Sn1B, Sn1B);
            prA_B = pack2(0.f, 0.f);
            prB_B = pack2(0.f, 0.f);
#pragma unroll
            for (int p = 0; p < NPAIR; p++) {
                u64 h = fma2(S0, p_m0[p], hbB[p]);
                h = fma2(S1, p_m1[p], h);
                hB[p] = h;
                u64 th = tanh2(h, C_2LOG2E2, C_ONE2, C_NEG22);
                float r0, r1; unpack2(th, r0, r1);
                prA_B = fma2(pack2(r0, r0), p_n01[2 * p],      prA_B);
                prB_B = fma2(pack2(r0, r0), p_wo01[2 * p],     prB_B);
                prA_B = fma2(pack2(r1, r1), p_n01[2 * p + 1],  prA_B);
                prB_B = fma2(pack2(r1, r1), p_wo01[2 * p + 1], prB_B);
            }
        }

        zcA = znA; zcB = znB;
        xcA0 = xnA0; xcA1 = xnA1; xcA2 = xnA2;
        xcB0 = xnB0; xcB1 = xnB1; xcB2 = xnB2;
    }

    // ---- epilogue: traj[T-1] both; final fold for out[T-1] both ----
    {
        float a0, a1, a2, a3;
        unpack2(hA[0], a0, a1);
        unpack2(hA[1], a2, a3);
        *(float4*)(trajpA + (size_t)(T_ - 1) * H_ + tid * 4) =
            make_float4(a0, a1, a2, a3);
        unpack2(hB[0], a0, a1);
        unpack2(hB[1], a2, a3);
        *(float4*)(trajpB + (size_t)(T_ - 1) * H_ + tid * 4) =
            make_float4(a0, a1, a2, a3);

        const int buf = T_ & 1;   // 0
        float v;
        {
            const bool kb = !(lane & 4);
            u64 sAx = kb ? prA_B : prA_A;
            u64 sBx = kb ? prB_B : prB_A;
            u64 rAx = __shfl_xor_sync(FULL, sAx, 4);
            u64 rBx = __shfl_xor_sync(FULL, sBx, 4);
            u64 qA = add2(kb ? prA_A : prA_B, rAx);
            u64 qB = add2(kb ? prB_A : prB_B, rBx);
            float px, py, pz, pw;
            unpack2(qA, px, py);
            unpack2(qB, pz, pw);
            const bool k1 = !(lane & 1);
            float sA = k1 ? pz : px;
            float rA = __shfl_xor_sync(FULL, sA, 1);
            float v0 = (k1 ? px : pz) + rA;
            float sB = k1 ? pw : py;
            float rB = __shfl_xor_sync(FULL, sB, 1);
            float v1 = (k1 ? py : pw) + rB;
            const bool k2 = !(lane & 2);
            float sC = k2 ? v1 : v0;
            float rC = __shfl_xor_sync(FULL, sC, 2);
            v = (k2 ? v0 : v1) + rC;
            v += __shfl_xor_sync(FULL, v, 8);
            v += __shfl_xor_sync(FULL, v, 16);
        }
        if (lane < 8) s_red[buf][warp * 8 + lane] = v;
        __syncthreads();
        if (warp == 0) {
            float u = s_red[buf][lane] + s_red[buf][lane + 32]
                    + s_red[buf][lane + 64] + s_red[buf][lane + 96];
            u += __shfl_xor_sync(FULL, u, 8);
            u += __shfl_xor_sync(FULL, u, 16);
            if (lane == 1) outpA[(T_ - 1) * O_ + 0] = u;
            if (lane == 3) outpA[(T_ - 1) * O_ + 1] = u;
            if (lane == 5) outpB[(T_ - 1) * O_ + 0] = u;
            if (lane == 7) outpB[(T_ - 1) * O_ + 1] = u;
        }
    }
}

extern "C" void kernel_launch(void* const* d_in, const int* in_sizes, int n_in,
                              void* d_out, int out_size) {
    (void)in_sizes; (void)n_in; (void)out_size;
    const float* input    = (const float*)d_in[0];
    const float* noise    = (const float*)d_in[1];
    const float* wi       = (const float*)d_in[2];
    const float* unitwi   = (const float*)d_in[3];
    const float* m        = (const float*)d_in[4];
    const float* n        = (const float*)d_in[5];
    const float* unitm    = (const float*)d_in[6];
    const float* unitn    = (const float*)d_in[7];
    const float* wo       = (const float*)d_in[8];
    const float* h0       = (const float*)d_in[9];
    const float* unith0   = (const float*)d_in[10];
    const float* bias     = (const float*)d_in[11];
    const float* gb       = (const float*)d_in[12];
    const float* uv       = (const float*)d_in[13];
    const float* sup      = (const float*)d_in[14];
    float* out            = (float*)d_out;

    lowrank_rnn_kernel<<<B_ / NBATCH, NTHREADS>>>(input, noise, wi, unitwi, m,
                                                  n, unitm, unitn, wo, h0,
                                                  unith0, bias, gb, uv, sup,
                                                  out);
}

// round 12
// speedup vs baseline: 1.8496x; 1.8496x over previous
#include <cuda_runtime.h>

// Problem constants
#define I_ 3
#define H_ 2048
#define O_ 2
#define R_ 2
#define S_ 4
#define G_ 7
#define B_ 32
#define T_ 512
#define ALPHA_ 0.2f
#define DECAY_ 0.8f
#define NSTD_ 0.05f

#define NTHREADS 512
#define NWARPS (NTHREADS / 32)   // 16
#define EPT 4                    // 512*4 = 2048 = H
#define NPART (NWARPS * 4)       // 64 partials per buffer

// HW MUFU tanh (sm_75+), single SASS instruction
__device__ __forceinline__ float tanh_hw(float x) {
    float r;
    asm("tanh.approx.f32 %0, %1;" : "=f"(r) : "f"(x));
    return r;
}

__global__ __launch_bounds__(NTHREADS, 1)
void lowrank_rnn_kernel(const float* __restrict__ input,   // (B,T,I)
                        const float* __restrict__ noise,   // (B,T,H)
                        const float* __restrict__ wi,      // (I,S,G)
                        const float* __restrict__ unitwi,  // (I,S,1)
                        const float* __restrict__ m,       // (R,S,G)
                        const float* __restrict__ n,       // (R,S,G)
                        const float* __restrict__ unitm,   // (R,S,1)
                        const float* __restrict__ unitn,   // (R,S,1)
                        const float* __restrict__ wo,      // (O,S,G)
                        const float* __restrict__ h0,      // (S,G)
                        const float* __restrict__ unith0,  // (S,1)
                        const float* __restrict__ bias,    // (S,1)
                        const float* __restrict__ gb,      // (G,H)
                        const float* __restrict__ uv,      // (1,H)
                        const float* __restrict__ sup,     // (S,H)
                        float* __restrict__ out)           // out(B,T,O) ++ traj(B,T,H)
{
    const int b    = blockIdx.x;
    const int tid  = threadIdx.x;
    const int lane = tid & 31;
    const int warp = tid >> 5;
    const unsigned FULL = 0xffffffffu;

    __shared__ float s_red[2 * NPART];

    // ------------------------------------------------------------------
    // Phase 1: per-element effective weights in registers (one-time).
    // ALPHA folded into c_m* / c_wi*.
    // ------------------------------------------------------------------
    float hreg[EPT];
    float c_m0[EPT], c_m1[EPT], c_n0[EPT], c_n1[EPT];
    float c_wo0[EPT], c_wo1[EPT], c_bias[EPT];
    float c_wi0[EPT], c_wi1[EPT], c_wi2[EPT];

#pragma unroll
    for (int e = 0; e < EPT; e++) {
        const int hidx = tid * EPT + e;
        float gvec[G_];
#pragma unroll
        for (int g = 0; g < G_; g++) gvec[g] = gb[g * H_ + hidx];
        const float uvh = uv[hidx];

        float awi0 = 0.f, awi1 = 0.f, awi2 = 0.f;
        float am0 = 0.f, am1 = 0.f, an0 = 0.f, an1 = 0.f;
        float awo0 = 0.f, awo1 = 0.f, ah0 = 0.f, ab = 0.f;

#pragma unroll
        for (int s = 0; s < S_; s++) {
            const float su = sup[s * H_ + hidx];

            float d0 = 0.f, d1 = 0.f, d2 = 0.f;
#pragma unroll
            for (int g = 0; g < G_; g++) {
                d0 += wi[(0 * S_ + s) * G_ + g] * gvec[g];
                d1 += wi[(1 * S_ + s) * G_ + g] * gvec[g];
                d2 += wi[(2 * S_ + s) * G_ + g] * gvec[g];
            }
            awi0 += (d0 + unitwi[0 * S_ + s] * uvh) * su;
            awi1 += (d1 + unitwi[1 * S_ + s] * uvh) * su;
            awi2 += (d2 + unitwi[2 * S_ + s] * uvh) * su;

            float dm0 = 0.f, dm1 = 0.f, dn0 = 0.f, dn1 = 0.f;
#pragma unroll
            for (int g = 0; g < G_; g++) {
                dm0 += m[(0 * S_ + s) * G_ + g] * gvec[g];
                dm1 += m[(1 * S_ + s) * G_ + g] * gvec[g];
                dn0 += n[(0 * S_ + s) * G_ + g] * gvec[g];
                dn1 += n[(1 * S_ + s) * G_ + g] * gvec[g];
            }
            am0 += (dm0 + unitm[0 * S_ + s] * uvh) * su;
            am1 += (dm1 + unitm[1 * S_ + s] * uvh) * su;
            an0 += (dn0 + unitn[0 * S_ + s] * uvh) * su;
            an1 += (dn1 + unitn[1 * S_ + s] * uvh) * su;

            float do0 = 0.f, do1 = 0.f, dh = 0.f;
#pragma unroll
            for (int g = 0; g < G_; g++) {
                do0 += wo[(0 * S_ + s) * G_ + g] * gvec[g];
                do1 += wo[(1 * S_ + s) * G_ + g] * gvec[g];
                dh  += h0[s * G_ + g] * gvec[g];
            }
            awo0 += do0 * su;
            awo1 += do1 * su;
            ah0  += dh * su + unith0[s] * uvh * su;
            ab   += bias[s] * uvh * su;
        }
        hreg[e]  = ah0;
        c_m0[e]  = ALPHA_ * am0;  c_m1[e]  = ALPHA_ * am1;
        c_n0[e]  = an0;           c_n1[e]  = an1;
        c_wo0[e] = awo0;          c_wo1[e] = awo1;
        c_bias[e] = ab;
        c_wi0[e] = ALPHA_ * awi0; c_wi1[e] = ALPHA_ * awi1;
        c_wi2[e] = ALPHA_ * awi2;
    }

    // ------------------------------------------------------------------
    // Phase 2: recurrence, software-pipelined (R4 schedule).
    // ------------------------------------------------------------------
    const float* zb = noise + (size_t)b * T_ * H_;
    const float* xb = input + (size_t)b * T_ * I_;
    float* outp  = out + (size_t)b * T_ * O_;
    float* trajp = out + (size_t)B_ * T_ * O_ + (size_t)b * T_ * H_;

    // pr for r_0 = tanh(h_0)
    float4 pr = make_float4(0.f, 0.f, 0.f, 0.f);
#pragma unroll
    for (int e = 0; e < EPT; e++) {
        float r = tanh_hw(hreg[e]);
        pr.x = fmaf(r, c_n0[e], pr.x);
        pr.y = fmaf(r, c_n1[e], pr.y);
        pr.z = fmaf(r, c_wo0[e], pr.z);
        pr.w = fmaf(r, c_wo1[e], pr.w);
    }

    // Prefetch noise / input two steps ahead
    float4 z0 = *(const float4*)(zb + 0 * (size_t)H_ + tid * 4);
    float4 z1 = *(const float4*)(zb + 1 * (size_t)H_ + tid * 4);
    float xA0 = xb[0], xA1 = xb[1], xA2 = xb[2];
    float xB0 = xb[3], xB1 = xb[4], xB2 = xb[5];

    for (int t = 0; t < T_; t++) {
        const int buf = t & 1;

        // ---- stage A: warp-level folded reduce (6 SHFL) ----
        {
            const bool k1 = !(lane & 1);
            float sA = k1 ? pr.z : pr.x;
            float rA = __shfl_xor_sync(FULL, sA, 1);
            float v0 = (k1 ? pr.x : pr.z) + rA;
            float sB = k1 ? pr.w : pr.y;
            float rB = __shfl_xor_sync(FULL, sB, 1);
            float v1 = (k1 ? pr.y : pr.w) + rB;
            const bool k2 = !(lane & 2);
            float sC = k2 ? v1 : v0;
            float rC = __shfl_xor_sync(FULL, sC, 2);
            float v  = (k2 ? v0 : v1) + rC;
            v += __shfl_xor_sync(FULL, v, 4);
            v += __shfl_xor_sync(FULL, v, 8);
            v += __shfl_xor_sync(FULL, v, 16);
            if (lane < 4) s_red[buf * NPART + warp * 4 + lane] = v;
        }

        // ---- stage B (shadow work, independent of the reduction) ----
        float base[EPT];
        {
            const float zarr[EPT] = {z0.x, z0.y, z0.z, z0.w};
#pragma unroll
            for (int e = 0; e < EPT; e++) {
                float bb = fmaf(hreg[e], DECAY_, c_bias[e]);
                bb = fmaf(zarr[e], NSTD_, bb);
                bb = fmaf(xA0, c_wi0[e], bb);
                bb = fmaf(xA1, c_wi1[e], bb);
                bb = fmaf(xA2, c_wi2[e], bb);
                base[e] = bb;
            }
        }
        const int tp = (t + 2 < T_) ? (t + 2) : (T_ - 1);
        float4 z2 = *(const float4*)(zb + (size_t)tp * H_ + tid * 4);
        const float xC0 = xb[tp * I_ + 0];
        const float xC1 = xb[tp * I_ + 1];
        const float xC2 = xb[tp * I_ + 2];

        __syncthreads();

        // ---- stage C: cross-warp reduce (LDS + 3 SHFL + 2 SHFL bcast) ----
        float Sn0, Sn1;
        {
            float u = s_red[buf * NPART + lane] + s_red[buf * NPART + 32 + lane];
            u += __shfl_xor_sync(FULL, u, 4);
            u += __shfl_xor_sync(FULL, u, 8);
            u += __shfl_xor_sync(FULL, u, 16);
            // lane&3: 0 -> n0, 1 -> wo0, 2 -> n1, 3 -> wo1
            Sn0 = __shfl_sync(FULL, u, 0);
            Sn1 = __shfl_sync(FULL, u, 2);
            if (warp == 0 && t > 0) {
                if (lane == 1) outp[(t - 1) * O_ + 0] = u;
                if (lane == 3) outp[(t - 1) * O_ + 1] = u;
            }
        }

        // ---- stage D: h_{t+1}, HW tanh, next pr, traj store ----
        pr = make_float4(0.f, 0.f, 0.f, 0.f);
        float hnew[EPT];
#pragma unroll
        for (int e = 0; e < EPT; e++) {
            float h = fmaf(Sn0, c_m0[e], fmaf(Sn1, c_m1[e], base[e]));
            hreg[e] = h;
            hnew[e] = h;
            float r = tanh_hw(h);
            pr.x = fmaf(r, c_n0[e], pr.x);
            pr.y = fmaf(r, c_n1[e], pr.y);
            pr.z = fmaf(r, c_wo0[e], pr.z);
            pr.w = fmaf(r, c_wo1[e], pr.w);
        }
        *(float4*)(trajp + (size_t)t * H_ + tid * 4) =
            make_float4(hnew[0], hnew[1], hnew[2], hnew[3]);

        z0 = z1; z1 = z2;
        xA0 = xB0; xA1 = xB1; xA2 = xB2;
        xB0 = xC0; xB1 = xC1; xB2 = xC2;
    }

    // ---- final reduce: out[T-1] = wo · tanh(h_T) ----
    {
        const int buf = T_ & 1;
        const bool k1 = !(lane & 1);
        float sA = k1 ? pr.z : pr.x;
        float rA = __shfl_xor_sync(FULL, sA, 1);
        float v0 = (k1 ? pr.x : pr.z) + rA;
        float sB = k1 ? pr.w : pr.y;
        float rB = __shfl_xor_sync(FULL, sB, 1);
        float v1 = (k1 ? pr.y : pr.w) + rB;
        const bool k2 = !(lane & 2);
        float sC = k2 ? v1 : v0;
        float rC = __shfl_xor_sync(FULL, sC, 2);
        float v  = (k2 ? v0 : v1) + rC;
        v += __shfl_xor_sync(FULL, v, 4);
        v += __shfl_xor_sync(FULL, v, 8);
        v += __shfl_xor_sync(FULL, v, 16);
        if (lane < 4) s_red[buf * NPART + warp * 4 + lane] = v;
        __syncthreads();
        if (warp == 0) {
            float u = s_red[buf * NPART + lane] + s_red[buf * NPART + 32 + lane];
            u += __shfl_xor_sync(FULL, u, 4);
            u += __shfl_xor_sync(FULL, u, 8);
            u += __shfl_xor_sync(FULL, u, 16);
            if (lane == 1) outp[(T_ - 1) * O_ + 0] = u;
            if (lane == 3) outp[(T_ - 1) * O_ + 1] = u;
        }
    }
}

extern "C" void kernel_launch(void* const* d_in, const int* in_sizes, int n_in,
                              void* d_out, int out_size) {
    (void)in_sizes; (void)n_in; (void)out_size;
    const float* input    = (const float*)d_in[0];
    const float* noise    = (const float*)d_in[1];
    const float* wi       = (const float*)d_in[2];
    const float* unitwi   = (const float*)d_in[3];
    const float* m        = (const float*)d_in[4];
    const float* n        = (const float*)d_in[5];
    const float* unitm    = (const float*)d_in[6];
    const float* unitn    = (const float*)d_in[7];
    const float* wo       = (const float*)d_in[8];
    const float* h0       = (const float*)d_in[9];
    const float* unith0   = (const float*)d_in[10];
    const float* bias     = (const float*)d_in[11];
    const float* gb       = (const float*)d_in[12];
    const float* uv       = (const float*)d_in[13];
    const float* sup      = (const float*)d_in[14];
    float* out            = (float*)d_out;

    lowrank_rnn_kernel<<<B_, NTHREADS>>>(input, noise, wi, unitwi, m, n, unitm,
                                         unitn, wo, h0, unith0, bias, gb, uv,
                                         sup, out);
}